// round 15
// baseline (speedup 1.0000x reference)
#include <cuda_runtime.h>
#include <math.h>

#define N   2048
#define D   4096
#define NC  8
#define ROWSTRIDE (2 * D)     // features is (N, 2, D); anchor = features[:,0,:]

#define MB 256   // blocks
#define MT 256   // threads
#define MR 8     // rows per block (natural rows 8b..8b+7, locally sorted by class)

// ---------------- device scratch (finalizer restores all state each run) ----------------
__device__ __align__(16) float gA[NC * D];   // per-class column sums of p (zeroed by finalizer)
__device__ __align__(16) float gX[NC * D];   // per-class column sums of x (zeroed by finalizer)
__device__ float  gEsum[NC];                 // reset by finalizer
__device__ float  gSsum[NC];                 // reset by finalizer
__device__ int    gCnt[NC];                  // class counts; reset by finalizer
__device__ int    g_done;                    // lights-out counter; reset by finalizer

// vector reduction to global (sm_100+: red.global.add.v4.f32)
__device__ __forceinline__ void redv4(float* p, float4 v) {
    asm volatile("red.global.add.v4.f32 [%0], {%1, %2, %3, %4};"
                 :: "l"(p), "f"(v.x), "f"(v.y), "f"(v.z), "f"(v.w) : "memory");
}

__global__ void __launch_bounds__(MT, 2) k_all(const float* __restrict__ feat,
                                               const int* __restrict__ labels,
                                               float* __restrict__ out) {
    const int b = blockIdx.x;
    const int t = threadIdx.x;
    const int wid = t >> 5, lane = t & 31;

    __shared__ int   sro[MR], scl[MR];
    __shared__ float sz[8], sw[8];
    __shared__ float sbinv;

    // thread 0: read this block's 8 labels, insertion-sort (class,row) pairs
    if (t == 0) {
        int rows[MR], cls[MR];
        #pragma unroll
        for (int j = 0; j < MR; j++) {
            rows[j] = b * MR + j;
            cls[j]  = labels[b * MR + j];
        }
        #pragma unroll
        for (int j = 1; j < MR; j++) {
            int cj = cls[j], rj = rows[j];
            int k = j - 1;
            while (k >= 0 && cls[k] > cj) {
                cls[k + 1] = cls[k];
                rows[k + 1] = rows[k];
                k--;
            }
            cls[k + 1] = cj;
            rows[k + 1] = rj;
        }
        #pragma unroll
        for (int j = 0; j < MR; j++) {
            sro[j] = rows[j] * ROWSTRIDE;
            scl[j] = cls[j];
        }
    }
    __syncthreads();

    float a[16], xs[16];
    #pragma unroll
    for (int q = 0; q < 16; q++) { a[q] = 0.f; xs[q] = 0.f; }
    float eacc = 0.f, sacc = 0.f;   // thread 0 only
    int rcnt = 0;                   // rows in current segment (thread 0 only)
    int cur = scl[0];

    // preload row 0 (thread owns float4 indices e*256+t, e=0..3)
    float4 v[4];
    {
        const float4* rp = (const float4*)(feat + sro[0]);
        #pragma unroll
        for (int e = 0; e < 4; e++) v[e] = __ldcg(rp + e * 256 + t);
    }

    #pragma unroll
    for (int r = 0; r < MR; r++) {
        // class-segment flush (uniform across block: local rows sorted by class)
        int cj = scl[r];
        if (cj != cur) {
            #pragma unroll
            for (int e = 0; e < 4; e++) {
                int k = (e * 256 + t) * 4;
                redv4(&gA[cur * D + k], make_float4(a[e*4], a[e*4+1], a[e*4+2], a[e*4+3]));
                redv4(&gX[cur * D + k], make_float4(xs[e*4], xs[e*4+1], xs[e*4+2], xs[e*4+3]));
            }
            #pragma unroll
            for (int q = 0; q < 16; q++) { a[q] = 0.f; xs[q] = 0.f; }
            if (t == 0) {
                atomicAdd(&gEsum[cur], eacc);
                atomicAdd(&gSsum[cur], sacc);
                atomicAdd(&gCnt[cur], rcnt);
                eacc = 0.f; sacc = 0.f; rcnt = 0;
            }
            cur = cj;
        }

        // prefetch next row while we compute this one
        float4 nv[4];
        if (r < MR - 1) {
            const float4* rp = (const float4*)(feat + sro[r + 1]);
            #pragma unroll
            for (int e = 0; e < 4; e++) nv[e] = __ldcg(rp + e * 256 + t);
        }

        // exp + accumulate x; v becomes q in place
        float z = 0.f, w = 0.f;
        #pragma unroll
        for (int e = 0; e < 4; e++) {
            float x0 = v[e].x, x1 = v[e].y, x2 = v[e].z, x3 = v[e].w;
            float q0 = __expf(x0), q1 = __expf(x1), q2 = __expf(x2), q3 = __expf(x3);
            z += q0 + q1 + q2 + q3;
            w = fmaf(q0, x0, w); w = fmaf(q1, x1, w);
            w = fmaf(q2, x2, w); w = fmaf(q3, x3, w);
            xs[e*4]   += x0; xs[e*4+1] += x1;
            xs[e*4+2] += x2; xs[e*4+3] += x3;
            v[e].x = q0; v[e].y = q1; v[e].z = q2; v[e].w = q3;
        }

        // block reduce Z, W
        #pragma unroll
        for (int o = 16; o; o >>= 1) {
            z += __shfl_xor_sync(0xffffffffu, z, o);
            w += __shfl_xor_sync(0xffffffffu, w, o);
        }
        if (lane == 0) { sz[wid] = z; sw[wid] = w; }
        __syncthreads();
        if (t == 0) {
            float Z = sz[0]+sz[1]+sz[2]+sz[3]+sz[4]+sz[5]+sz[6]+sz[7];
            float W = sw[0]+sw[1]+sw[2]+sw[3]+sw[4]+sw[5]+sw[6]+sw[7];
            float s = __logf(Z);            // logsumexp (no shift; data ~N(0,1))
            eacc += W / Z - s;              // row entropy term
            sacc += s;
            rcnt += 1;
            sbinv = 1.0f / Z;
        }
        __syncthreads();
        const float invZ = sbinv;

        // a += q * invZ
        #pragma unroll
        for (int e = 0; e < 4; e++) {
            a[e*4]   = fmaf(v[e].x, invZ, a[e*4]);
            a[e*4+1] = fmaf(v[e].y, invZ, a[e*4+1]);
            a[e*4+2] = fmaf(v[e].z, invZ, a[e*4+2]);
            a[e*4+3] = fmaf(v[e].w, invZ, a[e*4+3]);
        }

        if (r < MR - 1) {
            #pragma unroll
            for (int e = 0; e < 4; e++) v[e] = nv[e];
        }
    }

    // final flush
    #pragma unroll
    for (int e = 0; e < 4; e++) {
        int k = (e * 256 + t) * 4;
        redv4(&gA[cur * D + k], make_float4(a[e*4], a[e*4+1], a[e*4+2], a[e*4+3]));
        redv4(&gX[cur * D + k], make_float4(xs[e*4], xs[e*4+1], xs[e*4+2], xs[e*4+3]));
    }
    if (t == 0) {
        atomicAdd(&gEsum[cur], eacc);
        atomicAdd(&gSsum[cur], sacc);
        atomicAdd(&gCnt[cur], rcnt);
    }

    // ===== lights-out: last-arriving block computes dots, finalizes, resets =====
    __threadfence();
    __syncthreads();
    __shared__ int slast;
    if (t == 0) slast = (atomicAdd(&g_done, 1) == MB - 1) ? 1 : 0;
    __syncthreads();
    if (!slast) return;
    __threadfence();

    // 9 double dot products over gA/gX (256 KB, L2-hot); zero in the same sweep
    double part[NC + 1];
    #pragma unroll
    for (int vv = 0; vv < NC + 1; vv++) part[vv] = 0.0;
    const float4 zf = make_float4(0.f, 0.f, 0.f, 0.f);
    #pragma unroll
    for (int it = 0; it < 4; it++) {
        int k0 = it * 1024 + t * 4;
        float at[4] = {0.f, 0.f, 0.f, 0.f};
        float xt[4] = {0.f, 0.f, 0.f, 0.f};
        #pragma unroll
        for (int c = 0; c < NC; c++) {
            float4 av = __ldcg((const float4*)&gA[c * D + k0]);
            float4 xv = __ldcg((const float4*)&gX[c * D + k0]);
            part[c] += (double)av.x * (double)xv.x + (double)av.y * (double)xv.y
                     + (double)av.z * (double)xv.z + (double)av.w * (double)xv.w;
            at[0] += av.x; at[1] += av.y; at[2] += av.z; at[3] += av.w;
            xt[0] += xv.x; xt[1] += xv.y; xt[2] += xv.z; xt[3] += xv.w;
            *(float4*)&gA[c * D + k0] = zf;     // zero for next replay
            *(float4*)&gX[c * D + k0] = zf;
        }
        #pragma unroll
        for (int q = 0; q < 4; q++) part[NC] += (double)at[q] * (double)xt[q];
    }

    __shared__ double dred[8][NC + 1];
    #pragma unroll
    for (int vv = 0; vv < NC + 1; vv++) {
        double x = part[vv];
        #pragma unroll
        for (int o = 16; o; o >>= 1) x += __shfl_xor_sync(0xffffffffu, x, o);
        if (lane == 0) dred[wid][vv] = x;
    }
    __syncthreads();

    if (t == 0) {
        double dots[NC + 1];
        #pragma unroll
        for (int vv = 0; vv < NC + 1; vv++) {
            double s = 0.0;
            #pragma unroll
            for (int w = 0; w < 8; w++) s += dred[w][vv];
            dots[vv] = s;
        }
        double same = 0.0, diff = 0.0, sumS = 0.0, Ss_tot = 0.0;
        for (int c = 0; c < NC; c++) {
            double n    = (double)gCnt[c];
            double Sc_s = (double)gSsum[c];
            double E    = (double)gEsum[c];
            double S    = dots[c] - Sc_s * n;       // dot(A_c, B_c)
            same += n * E - S;
            diff += ((double)N - n) * E;
            sumS += S;
            Ss_tot += Sc_s;
        }
        double Stot = dots[NC] - Ss_tot * (double)N;
        diff -= (Stot - sumS);
        out[0] = (float)(same / diff);

        // reset remaining state for next graph replay
        for (int c = 0; c < NC; c++) { gEsum[c] = 0.f; gSsum[c] = 0.f; gCnt[c] = 0; }
        g_done = 0;
        __threadfence();
    }
}

extern "C" void kernel_launch(void* const* d_in, const int* in_sizes, int n_in,
                              void* d_out, int out_size) {
    const float* feat   = (const float*)d_in[0];
    const int*   labels = (const int*)d_in[1];
    float*       out    = (float*)d_out;
    (void)in_sizes; (void)n_in; (void)out_size;

    k_all<<<MB, MT>>>(feat, labels, out);
}

// round 16
// speedup vs baseline: 1.0060x; 1.0060x over previous
#include <cuda_runtime.h>
#include <math.h>

#define N   2048
#define D   4096
#define NC  8
#define ROWSTRIDE (2 * D)     // features is (N, 2, D); anchor = features[:,0,:]

#define MB 256   // blocks
#define MT 256   // threads
#define MR 8     // rows per block (natural rows 8b..8b+7, locally sorted by class)

// ---------------- device scratch (finalizer restores all state each run) ----------------
__device__ __align__(16) float gA[NC * D];   // per-class column sums of p (zeroed by finalizer)
__device__ __align__(16) float gX[NC * D];   // per-class column sums of x (zeroed by finalizer)
__device__ float  gEsum[NC];                 // reset by finalizer
__device__ float  gSsum[NC];                 // reset by finalizer
__device__ int    gCnt[NC];                  // class counts; reset by finalizer
__device__ int    g_done;                    // lights-out counter; reset by finalizer

// vector reduction to global (sm_100+: red.global.add.v4.f32)
__device__ __forceinline__ void redv4(float* p, float4 v) {
    asm volatile("red.global.add.v4.f32 [%0], {%1, %2, %3, %4};"
                 :: "l"(p), "f"(v.x), "f"(v.y), "f"(v.z), "f"(v.w) : "memory");
}

__global__ void __launch_bounds__(MT, 2) k_all(const float* __restrict__ feat,
                                               const int* __restrict__ labels,
                                               float* __restrict__ out) {
    const int b = blockIdx.x;
    const int t = threadIdx.x;
    const int wid = t >> 5, lane = t & 31;

    __shared__ int   sro[MR], scl[MR];
    __shared__ float sz[8], sw[8];
    __shared__ float sbinv;

    // thread 0: read this block's 8 labels, insertion-sort (class,row) pairs
    if (t == 0) {
        int rows[MR], cls[MR];
        #pragma unroll
        for (int j = 0; j < MR; j++) {
            rows[j] = b * MR + j;
            cls[j]  = labels[b * MR + j];
        }
        #pragma unroll
        for (int j = 1; j < MR; j++) {
            int cj = cls[j], rj = rows[j];
            int k = j - 1;
            while (k >= 0 && cls[k] > cj) {
                cls[k + 1] = cls[k];
                rows[k + 1] = rows[k];
                k--;
            }
            cls[k + 1] = cj;
            rows[k + 1] = rj;
        }
        #pragma unroll
        for (int j = 0; j < MR; j++) {
            sro[j] = rows[j] * ROWSTRIDE;
            scl[j] = cls[j];
        }
    }
    __syncthreads();

    {   // ===== main phase (proven R14 loop) =====
        float a[16], xs[16];
        #pragma unroll
        for (int q = 0; q < 16; q++) { a[q] = 0.f; xs[q] = 0.f; }
        float eacc = 0.f, sacc = 0.f;   // thread 0 only
        int rcnt = 0;                   // rows in current segment (thread 0 only)
        int cur = scl[0];

        float4 v[4];
        {
            const float4* rp = (const float4*)(feat + sro[0]);
            #pragma unroll
            for (int e = 0; e < 4; e++) v[e] = __ldcg(rp + e * 256 + t);
        }

        #pragma unroll
        for (int r = 0; r < MR; r++) {
            int cj = scl[r];
            if (cj != cur) {    // uniform across block (local rows sorted by class)
                #pragma unroll
                for (int e = 0; e < 4; e++) {
                    int k = (e * 256 + t) * 4;
                    redv4(&gA[cur * D + k], make_float4(a[e*4], a[e*4+1], a[e*4+2], a[e*4+3]));
                    redv4(&gX[cur * D + k], make_float4(xs[e*4], xs[e*4+1], xs[e*4+2], xs[e*4+3]));
                }
                #pragma unroll
                for (int q = 0; q < 16; q++) { a[q] = 0.f; xs[q] = 0.f; }
                if (t == 0) {
                    atomicAdd(&gEsum[cur], eacc);
                    atomicAdd(&gSsum[cur], sacc);
                    atomicAdd(&gCnt[cur], rcnt);
                    eacc = 0.f; sacc = 0.f; rcnt = 0;
                }
                cur = cj;
            }

            float4 nv[4];
            if (r < MR - 1) {
                const float4* rp = (const float4*)(feat + sro[r + 1]);
                #pragma unroll
                for (int e = 0; e < 4; e++) nv[e] = __ldcg(rp + e * 256 + t);
            }

            float z = 0.f, w = 0.f;
            #pragma unroll
            for (int e = 0; e < 4; e++) {
                float x0 = v[e].x, x1 = v[e].y, x2 = v[e].z, x3 = v[e].w;
                float q0 = __expf(x0), q1 = __expf(x1), q2 = __expf(x2), q3 = __expf(x3);
                z += q0 + q1 + q2 + q3;
                w = fmaf(q0, x0, w); w = fmaf(q1, x1, w);
                w = fmaf(q2, x2, w); w = fmaf(q3, x3, w);
                xs[e*4]   += x0; xs[e*4+1] += x1;
                xs[e*4+2] += x2; xs[e*4+3] += x3;
                v[e].x = q0; v[e].y = q1; v[e].z = q2; v[e].w = q3;
            }

            #pragma unroll
            for (int o = 16; o; o >>= 1) {
                z += __shfl_xor_sync(0xffffffffu, z, o);
                w += __shfl_xor_sync(0xffffffffu, w, o);
            }
            if (lane == 0) { sz[wid] = z; sw[wid] = w; }
            __syncthreads();
            if (t == 0) {
                float Z = sz[0]+sz[1]+sz[2]+sz[3]+sz[4]+sz[5]+sz[6]+sz[7];
                float W = sw[0]+sw[1]+sw[2]+sw[3]+sw[4]+sw[5]+sw[6]+sw[7];
                float s = __logf(Z);        // logsumexp (no shift; data ~N(0,1))
                eacc += W / Z - s;
                sacc += s;
                rcnt += 1;
                sbinv = 1.0f / Z;
            }
            __syncthreads();
            const float invZ = sbinv;

            #pragma unroll
            for (int e = 0; e < 4; e++) {
                a[e*4]   = fmaf(v[e].x, invZ, a[e*4]);
                a[e*4+1] = fmaf(v[e].y, invZ, a[e*4+1]);
                a[e*4+2] = fmaf(v[e].z, invZ, a[e*4+2]);
                a[e*4+3] = fmaf(v[e].w, invZ, a[e*4+3]);
            }

            if (r < MR - 1) {
                #pragma unroll
                for (int e = 0; e < 4; e++) v[e] = nv[e];
            }
        }

        // final flush
        #pragma unroll
        for (int e = 0; e < 4; e++) {
            int k = (e * 256 + t) * 4;
            redv4(&gA[cur * D + k], make_float4(a[e*4], a[e*4+1], a[e*4+2], a[e*4+3]));
            redv4(&gX[cur * D + k], make_float4(xs[e*4], xs[e*4+1], xs[e*4+2], xs[e*4+3]));
        }
        if (t == 0) {
            atomicAdd(&gEsum[cur], eacc);
            atomicAdd(&gSsum[cur], sacc);
            atomicAdd(&gCnt[cur], rcnt);
        }
    }   // main-phase registers (a, xs, v, nv) die here

    // ===== lights-out: last-arriving block finalizes (register-lean tail) =====
    __threadfence();
    __syncthreads();
    __shared__ int slast;
    if (t == 0) slast = (atomicAdd(&g_done, 1) == MB - 1) ? 1 : 0;
    __syncthreads();
    if (!slast) return;
    __threadfence();

    __shared__ double d8[8];     // totals-dot partials per warp
    __shared__ double dcls[8];   // per-class dots

    // ---- Stage T2: totals dot  Stot_part = sum_k (sum_c A)(sum_c X) ----
    {
        double p8 = 0.0;
        for (int k = t; k < D; k += MT) {
            float at = 0.f, xt = 0.f;
            #pragma unroll
            for (int c = 0; c < NC; c++) {
                at += __ldcg(&gA[c * D + k]);
                xt += __ldcg(&gX[c * D + k]);
            }
            p8 += (double)at * (double)xt;
        }
        #pragma unroll
        for (int o = 16; o; o >>= 1) p8 += __shfl_xor_sync(0xffffffffu, p8, o);
        if (lane == 0) d8[wid] = p8;
    }
    __syncthreads();   // all stage-T2 reads complete before T1 zeroes

    // ---- Stage T1: warp c computes dots[c] and zeroes class c's slices ----
    {
        const int c = wid;   // 8 warps == NC classes
        float4* pa = (float4*)&gA[c * D];
        float4* px = (float4*)&gX[c * D];
        const float4 zf = make_float4(0.f, 0.f, 0.f, 0.f);
        double pc = 0.0;
        for (int i = lane; i < D / 4; i += 32) {
            float4 av = __ldcg((const float4*)(pa + i));
            float4 xv = __ldcg((const float4*)(px + i));
            pc += (double)av.x * (double)xv.x + (double)av.y * (double)xv.y
                + (double)av.z * (double)xv.z + (double)av.w * (double)xv.w;
            pa[i] = zf;      // zero for next replay
            px[i] = zf;
        }
        #pragma unroll
        for (int o = 16; o; o >>= 1) pc += __shfl_xor_sync(0xffffffffu, pc, o);
        if (lane == 0) dcls[c] = pc;
    }
    __syncthreads();

    if (t == 0) {
        double Stot_raw = d8[0]+d8[1]+d8[2]+d8[3]+d8[4]+d8[5]+d8[6]+d8[7];
        double same = 0.0, diff = 0.0, sumS = 0.0, Ss_tot = 0.0;
        for (int c = 0; c < NC; c++) {
            double n    = (double)gCnt[c];
            double Sc_s = (double)gSsum[c];
            double E    = (double)gEsum[c];
            double S    = dcls[c] - Sc_s * n;       // dot(A_c, B_c)
            same += n * E - S;
            diff += ((double)N - n) * E;
            sumS += S;
            Ss_tot += Sc_s;
        }
        double Stot = Stot_raw - Ss_tot * (double)N;
        diff -= (Stot - sumS);
        out[0] = (float)(same / diff);

        // reset remaining state for next graph replay
        for (int c = 0; c < NC; c++) { gEsum[c] = 0.f; gSsum[c] = 0.f; gCnt[c] = 0; }
        g_done = 0;
        __threadfence();
    }
}

extern "C" void kernel_launch(void* const* d_in, const int* in_sizes, int n_in,
                              void* d_out, int out_size) {
    const float* feat   = (const float*)d_in[0];
    const int*   labels = (const int*)d_in[1];
    float*       out    = (float*)d_out;
    (void)in_sizes; (void)n_in; (void)out_size;

    k_all<<<MB, MT>>>(feat, labels, out);
}

// round 17
// speedup vs baseline: 2.0503x; 2.0379x over previous
#include <cuda_runtime.h>
#include <math.h>

#define N   2048
#define D   4096
#define NC  8
#define ROWSTRIDE (2 * D)     // features is (N, 2, D); anchor = features[:,0,:]

// ---------------- device scratch ----------------
__device__ int    g_order[N];
__device__ int    g_cls[N];
__device__ int    g_counts[NC];
__device__ __align__(16) float gA[NC * D];   // per-class column sums of p (zeroed by k3 each run)
__device__ __align__(16) float gX[NC * D];   // per-class column sums of x (zeroed by k3 each run)
__device__ double g_dot[NC + 1];             // reset by k3 finalizer
__device__ float  gEsum[NC];                 // reset by k3 finalizer
__device__ float  gSsum[NC];                 // reset by k3 finalizer
__device__ int    g_xdone[4];                // per-column-slice counters (reset by finalizer)
__device__ int    g_done;                    // lights-out counter (reset by finalizer)

// vector reduction to global (sm_100+: red.global.add.v4.f32)
__device__ __forceinline__ void redv4(float* p, float4 v) {
    asm volatile("red.global.add.v4.f32 [%0], {%1, %2, %3, %4};"
                 :: "l"(p), "f"(v.x), "f"(v.y), "f"(v.z), "f"(v.w) : "memory");
}

// ================= K0: ATOMIC-FREE counting sort (1 block, warp scans) =================
__global__ void __launch_bounds__(256) k0_sort(const int* __restrict__ labels) {
    const int t = threadIdx.x;
    const int wid = t >> 5, lane = t & 31;

    __shared__ int scnt[256 * NC];    // per-thread counts -> exclusive prefixes (8 KB)
    __shared__ int stot[NC], soff[NC];

    int4 la = __ldg((const int4*)(labels + 8 * t));
    int4 lb = __ldg((const int4*)(labels + 8 * t + 4));
    int larr[8] = {la.x, la.y, la.z, la.w, lb.x, lb.y, lb.z, lb.w};

    #pragma unroll
    for (int c = 0; c < NC; c++) {
        int cc = 0;
        #pragma unroll
        for (int j = 0; j < 8; j++) cc += (larr[j] == c);
        scnt[t * NC + c] = cc;
    }
    __syncthreads();

    // warp w scans class w over the 256 thread entries (lane owns 8 consecutive entries)
    {
        const int c = wid;
        int vals[8], s = 0;
        #pragma unroll
        for (int j = 0; j < 8; j++) { vals[j] = scnt[(lane * 8 + j) * NC + c]; s += vals[j]; }
        int incl = s;
        #pragma unroll
        for (int o = 1; o < 32; o <<= 1) {
            int nvv = __shfl_up_sync(0xffffffffu, incl, o);
            if (lane >= o) incl += nvv;
        }
        int total = __shfl_sync(0xffffffffu, incl, 31);
        int run = incl - s;   // exclusive prefix for this lane's chunk
        #pragma unroll
        for (int j = 0; j < 8; j++) { scnt[(lane * 8 + j) * NC + c] = run; run += vals[j]; }
        if (lane == 0) stot[c] = total;
    }
    __syncthreads();
    if (t == 0) {
        int run = 0;
        #pragma unroll
        for (int c = 0; c < NC; c++) {
            soff[c] = run;
            g_counts[c] = stot[c];
            run += stot[c];
        }
    }
    __syncthreads();

    // direct placement, no atomics
    #pragma unroll
    for (int j = 0; j < 8; j++) {
        int c = larr[j];
        int seen = 0;
        #pragma unroll
        for (int jj = 0; jj < 8; jj++) if (jj < j) seen += (larr[jj] == c);
        int pos = soff[c] + scnt[t * NC + c] + seen;
        g_order[pos] = 8 * t + j;
        g_cls[pos]   = c;
    }
}

// ================= K_MAIN: fused pass, occupancy 4, no software prefetch =================
#define MB 256   // blocks
#define MT 256   // threads
#define MR 8     // globally-sorted rows per block

__global__ void __launch_bounds__(MT, 4) k_main(const float* __restrict__ feat) {
    const int b = blockIdx.x;
    const int t = threadIdx.x;

    __shared__ int   sro[MR], scl[MR];
    __shared__ float sz[8], sw[8];
    __shared__ float sbinv;
    if (t < MR) {
        int idx = b * MR + t;
        sro[t] = g_order[idx] * ROWSTRIDE;
        scl[t] = g_cls[idx];
    }
    __syncthreads();

    float a[16], xs[16];
    #pragma unroll
    for (int q = 0; q < 16; q++) { a[q] = 0.f; xs[q] = 0.f; }
    float eacc = 0.f, sacc = 0.f;   // thread 0 only
    int cur = scl[0];

    #pragma unroll
    for (int r = 0; r < MR; r++) {
        // class-segment flush (uniform across block: rows globally sorted by class)
        int cj = scl[r];
        if (cj != cur) {
            #pragma unroll
            for (int e = 0; e < 4; e++) {
                int k = (e * 256 + t) * 4;
                redv4(&gA[cur * D + k], make_float4(a[e*4], a[e*4+1], a[e*4+2], a[e*4+3]));
                redv4(&gX[cur * D + k], make_float4(xs[e*4], xs[e*4+1], xs[e*4+2], xs[e*4+3]));
            }
            #pragma unroll
            for (int q = 0; q < 16; q++) { a[q] = 0.f; xs[q] = 0.f; }
            if (t == 0) {
                atomicAdd(&gEsum[cur], eacc);
                atomicAdd(&gSsum[cur], sacc);
                eacc = 0.f; sacc = 0.f;
            }
            cur = cj;
        }

        // load row r (4 float4 per thread; TLP hides latency at occ 4)
        float4 v[4];
        {
            const float4* rp = (const float4*)(feat + sro[r]);
            #pragma unroll
            for (int e = 0; e < 4; e++) v[e] = __ldcg(rp + e * 256 + t);
        }

        // exp + accumulate x; v becomes q in place
        float z = 0.f, w = 0.f;
        #pragma unroll
        for (int e = 0; e < 4; e++) {
            float x0 = v[e].x, x1 = v[e].y, x2 = v[e].z, x3 = v[e].w;
            float q0 = __expf(x0), q1 = __expf(x1), q2 = __expf(x2), q3 = __expf(x3);
            z += q0 + q1 + q2 + q3;
            w = fmaf(q0, x0, w); w = fmaf(q1, x1, w);
            w = fmaf(q2, x2, w); w = fmaf(q3, x3, w);
            xs[e*4]   += x0; xs[e*4+1] += x1;
            xs[e*4+2] += x2; xs[e*4+3] += x3;
            v[e].x = q0; v[e].y = q1; v[e].z = q2; v[e].w = q3;
        }

        // block reduce Z, W
        #pragma unroll
        for (int o = 16; o; o >>= 1) {
            z += __shfl_xor_sync(0xffffffffu, z, o);
            w += __shfl_xor_sync(0xffffffffu, w, o);
        }
        if ((t & 31) == 0) { sz[t >> 5] = z; sw[t >> 5] = w; }
        __syncthreads();
        if (t == 0) {
            float Z = sz[0]+sz[1]+sz[2]+sz[3]+sz[4]+sz[5]+sz[6]+sz[7];
            float W = sw[0]+sw[1]+sw[2]+sw[3]+sw[4]+sw[5]+sw[6]+sw[7];
            float s = __logf(Z);            // logsumexp (no shift; data ~N(0,1))
            eacc += W / Z - s;              // row entropy term
            sacc += s;
            sbinv = 1.0f / Z;
        }
        __syncthreads();
        const float invZ = sbinv;

        // a += q * invZ
        #pragma unroll
        for (int e = 0; e < 4; e++) {
            a[e*4]   = fmaf(v[e].x, invZ, a[e*4]);
            a[e*4+1] = fmaf(v[e].y, invZ, a[e*4+1]);
            a[e*4+2] = fmaf(v[e].z, invZ, a[e*4+2]);
            a[e*4+3] = fmaf(v[e].w, invZ, a[e*4+3]);
        }
    }

    // final flush
    #pragma unroll
    for (int e = 0; e < 4; e++) {
        int k = (e * 256 + t) * 4;
        redv4(&gA[cur * D + k], make_float4(a[e*4], a[e*4+1], a[e*4+2], a[e*4+3]));
        redv4(&gX[cur * D + k], make_float4(xs[e*4], xs[e*4+1], xs[e*4+2], xs[e*4+3]));
    }
    if (t == 0) {
        atomicAdd(&gEsum[cur], eacc);
        atomicAdd(&gSsum[cur], sacc);
    }
}

// ================= K3: dots + slice zeroing + lights-out finalize (36 blocks) =================
#define K3BLK 36

__global__ void __launch_bounds__(256) k3_dots(float* __restrict__ out) {
    const int t = threadIdx.x;
    const int c = blockIdx.y;                 // 0..NC  (NC = totals)
    const int x = blockIdx.x;                 // column slice (4 x 1024 cols)
    const int k0 = x * 1024 + t * 4;

    double part = 0.0;
    if (c < NC) {
        float4 a = *(const float4*)&gA[c * D + k0];
        float4 xv = *(const float4*)&gX[c * D + k0];
        part = (double)a.x * (double)xv.x + (double)a.y * (double)xv.y
             + (double)a.z * (double)xv.z + (double)a.w * (double)xv.w;
    } else {
        float at[4] = {0.f, 0.f, 0.f, 0.f};
        float xt[4] = {0.f, 0.f, 0.f, 0.f};
        #pragma unroll
        for (int cc = 0; cc < NC; cc++) {
            float4 a = *(const float4*)&gA[cc * D + k0];
            float4 xv = *(const float4*)&gX[cc * D + k0];
            at[0] += a.x; at[1] += a.y; at[2] += a.z; at[3] += a.w;
            xt[0] += xv.x; xt[1] += xv.y; xt[2] += xv.z; xt[3] += xv.w;
        }
        #pragma unroll
        for (int q = 0; q < 4; q++) part += (double)at[q] * (double)xt[q];
    }

    #pragma unroll
    for (int o = 16; o; o >>= 1) part += __shfl_xor_sync(0xffffffffu, part, o);
    __shared__ double red[8];
    if ((t & 31) == 0) red[t >> 5] = part;
    __syncthreads();
    if (t == 0) {
        double s = 0.0;
        #pragma unroll
        for (int w = 0; w < 8; w++) s += red[w];
        atomicAdd(&g_dot[c], s);
    }

    // ---- per-slice zeroing: 9th block of this column-slice zeroes it for the next run ----
    __shared__ int szero;
    __syncthreads();
    if (t == 0) szero = (atomicAdd(&g_xdone[x], 1) == NC) ? 1 : 0;   // 9 blocks per x
    __syncthreads();
    if (szero) {
        for (int idx = t; idx < NC * 1024; idx += 256) {
            int cc = idx >> 10, j = idx & 1023;
            gA[cc * D + x * 1024 + j] = 0.f;
            gX[cc * D + x * 1024 + j] = 0.f;
        }
    }

    // ---- lights-out: 36th arriving block finalizes (scalar work only) ----
    __threadfence();
    __syncthreads();
    __shared__ int slast;
    if (t == 0) slast = (atomicAdd(&g_done, 1) == K3BLK - 1) ? 1 : 0;
    __syncthreads();
    if (!slast) return;

    if (t == 0) {
        __threadfence();
        double same = 0.0, diff = 0.0, sumS = 0.0, Ss_tot = 0.0;
        for (int cc = 0; cc < NC; cc++) {
            double n    = (double)g_counts[cc];
            double Sc_s = (double)gSsum[cc];
            double E    = (double)gEsum[cc];
            double S    = g_dot[cc] - Sc_s * n;      // dot(A_c, B_c)
            same += n * E - S;
            diff += ((double)N - n) * E;
            sumS += S;
            Ss_tot += Sc_s;
        }
        double Stot = g_dot[NC] - Ss_tot * (double)N;
        diff -= (Stot - sumS);
        out[0] = (float)(same / diff);

        // reset everything for the next graph replay
        for (int cc = 0; cc < NC; cc++) { gEsum[cc] = 0.f; gSsum[cc] = 0.f; }
        for (int v = 0; v < NC + 1; v++) g_dot[v] = 0.0;
        g_xdone[0] = g_xdone[1] = g_xdone[2] = g_xdone[3] = 0;
        g_done = 0;
        __threadfence();
    }
}

extern "C" void kernel_launch(void* const* d_in, const int* in_sizes, int n_in,
                              void* d_out, int out_size) {
    const float* feat   = (const float*)d_in[0];
    const int*   labels = (const int*)d_in[1];
    float*       out    = (float*)d_out;
    (void)in_sizes; (void)n_in; (void)out_size;

    k0_sort<<<1, 256>>>(labels);
    k_main<<<MB, MT>>>(feat);
    k3_dots<<<dim3(4, NC + 1), 256>>>(out);
}